// round 17
// baseline (speedup 1.0000x reference)
#include <cuda_runtime.h>
#include <cstdint>

// Problem constants: B=128, T=2048, D=256, LAMDA=0.5
#define B_ 128
#define T_ 2048
#define D_ 256
#define S_ 32                          // 64-row chunks per (b, tensor)
#define ROWS_ITEM 64
#define NW 4                           // warps per CTA (small CTA -> cheap flush)
#define NTHREADS 128
#define OCC 5                          // CTAs/SM (regs ~96 for triple-buffer)
#define GRID_MAIN (148 * OCC)          // 740 — single wave at occupancy 5
#define CPT (GRID_MAIN / 2)            // 370 CTAs per tensor type
#define NIT (B_ * S_)                  // 4096 chunks per tensor
#define NDOTS (B_ * D_)                // 32768 mids row-dots
#define ROWS_W (ROWS_ITEM / NW)        // 16 rows per warp per chunk
#define NPAIR (ROWS_W / 2)             // 8 row-pairs per warp per chunk

// Globals (zero-initialized). Counters monotonic+modular -> graph-replay safe.
// Partials are written fresh every launch before being read (proven scheme).
__device__ float g_mids[B_ * D_];
__device__ float g_pa[NIT][258];   // aspect partials (acc[256], L at [256])
__device__ float g_p1[NIT][258];   // sentiment-sentiment partials
__device__ float g_p2[NIT][258];   // sentiment-aspect partials
__device__ unsigned g_bar;         // aspect-side barrier counter (+CPT/launch)
__device__ unsigned g_cnt_s[B_];   // sentiment chunk counters (+32/launch)
__device__ unsigned g_cnt_a[B_];   // aspect chunk counters    (+32/launch)

__device__ __forceinline__ float warp_sum(float v) {
#pragma unroll
    for (int o = 16; o > 0; o >>= 1) v += __shfl_xor_sync(0xffffffffu, v, o);
    return v;
}
__device__ __forceinline__ float dot8(float4 a, float4 b, float4 c, float4 d) {
    return a.x*b.x + a.y*b.y + a.z*b.z + a.w*b.w
         + c.x*d.x + c.y*d.y + c.z*d.z + c.w*d.w;
}
// Fast tanh (inf-safe |x| form; exact +-1 saturation at large |x|).
__device__ __forceinline__ float fast_tanh(float x) {
    const float t = __expf(2.0f * fabsf(x));
    const float r = 1.0f - __fdividef(2.0f, t + 1.0f);
    return copysignf(r, x);
}
#define FMA4(acc, s, r) \
    acc.x += (s)*(r).x; acc.y += (s)*(r).y; acc.z += (s)*(r).z; acc.w += (s)*(r).w;

// ---------------------------------------------------------------------------
// k_main: ONE kernel, grid = 740 (5 CTAs/SM, single wave). Inner loops are
// software-pipelined with PREFETCH DEPTH 2 (triple buffer): pair p+2's
// 4 LDG.128s are issued ~2 compute phases (~500 cyc) before consumption,
// covering the ~600-cyc DRAM latency (depth 1 covered only ~250 cyc and
// capped DRAM at 53% in R16). Mod-3 slot rotation in a fully-unrolled loop
// constant-folds into pure register renaming (~96 regs -> occupancy 5).
// Proven cross-CTA protocol: per-chunk partial arrays (plain STGs) +
// per-chunk counter; the CTA seeing (old&31)==31 for b does b's combine.
// Even CTAs: mids GEMV -> barrier (aspect half only) -> stream aspect_memory.
// Odd CTAs:  stream sentiment_memory immediately (two softmax streams).
// No online max needed: aspect scores = tanh in [-1,1]; sentiment scores are
// O(1) -> plain exp() is safe and equals the reference's shifted softmax.
// Query-side additive terms are constant over t and cancel in the softmax.
// ---------------------------------------------------------------------------
__global__ void __launch_bounds__(NTHREADS, OCC) k_main(
    const float* __restrict__ aspect,            // [B,D]
    const float* __restrict__ sentiment_memory,  // [B,T,D]
    const float* __restrict__ aspect_memory,     // [B,T,D]
    const float* __restrict__ mask,              // [B,T]
    const float* __restrict__ W_mul,             // [D,D]
    const float* __restrict__ b_mul,             // [1]
    const float* __restrict__ w_ss,              // [2D] (only [:D] matters)
    const float* __restrict__ w_sa,              // [2D]
    float* __restrict__ out)                     // [2*B*D]
{
    __shared__ __align__(16) float s_red[2 * NW * D_];   // 8 KB (P half, Q half)
    __shared__ float s_lred[2 * NW];
    __shared__ int s_doc;

    const int cta   = blockIdx.x;
    const int ctype = cta & 1;          // 0 = aspect, 1 = sentiment
    const int tcta  = cta >> 1;
    const int tid   = threadIdx.x;
    const int w     = tid >> 5, lane = tid & 31;

    const int nit = (NIT - tcta + CPT - 1) / CPT;   // 11 or 12 chunks

    if (ctype == 0) {
        // ---- mids GEMV by aspect CTAs only (sentiment half streams now) ----
        const int gid = tcta * NW + w;
        for (int idx = gid; idx < NDOTS; idx += CPT * NW) {
            const int b   = idx >> 8;
            const int row = idx & (D_ - 1);
            const float4* Wr = (const float4*)(W_mul + (size_t)row * D_);
            const float4* Ar = (const float4*)(aspect + (size_t)b * D_);
            float p = dot8(Wr[lane], Ar[lane], Wr[32 + lane], Ar[32 + lane]);
            p = warp_sum(p);
            if (lane == 0) g_mids[b * D_ + row] = p;
        }
        __threadfence();   // release own g_mids writes (every thread)
        __syncthreads();
        // Replay-safe barrier among the CPT aspect CTAs (monotonic counter).
        if (tid == 0) {
            const unsigned old = atomicAdd(&g_bar, 1u);
            const unsigned tgt = (old / CPT + 1u) * CPT;
            while (*(volatile unsigned*)&g_bar < tgt) { }
        }
        __syncthreads();
        __threadfence();   // acquire
    }

    if (ctype == 1) {
        // ------------- sentiment: two softmax streams -------------
        const float4 w10 = *(const float4*)(w_ss + lane * 4);
        const float4 w11 = *(const float4*)(w_ss + 128 + lane * 4);
        const float4 w20 = *(const float4*)(w_sa + lane * 4);
        const float4 w21 = *(const float4*)(w_sa + 128 + lane * 4);

        for (int j = 0; j < nit; j++) {
            const int e = tcta + CPT * j;
            const int b = e >> 5, s = e & 31;
            const float4* m4  = (const float4*)(sentiment_memory
                              + ((size_t)b * T_ + (size_t)s * ROWS_ITEM
                                 + w * ROWS_W) * D_);
            const float* mrow = mask + (size_t)b * T_ + (size_t)s * ROWS_ITEM
                              + w * ROWS_W;

            float l1 = 0.f, l2 = 0.f;
            float4 P0 = {0,0,0,0}, P1 = {0,0,0,0};
            float4 Q0 = {0,0,0,0}, Q1 = {0,0,0,0};

            // Triple-buffered pipeline: slots hold pairs p, p+1, p+2.
            float4 bA0[3], bA1[3], bB0[3], bB1[3];
            float  bMa[3], bMb[3];
#pragma unroll
            for (int k = 0; k < 2; k++) {     // preload pairs 0,1
                const int r2 = 2 * k;
                bA0[k] = __ldcs(&m4[(size_t)r2 * 64 + lane]);
                bA1[k] = __ldcs(&m4[(size_t)r2 * 64 + 32 + lane]);
                bB0[k] = __ldcs(&m4[(size_t)(r2 + 1) * 64 + lane]);
                bB1[k] = __ldcs(&m4[(size_t)(r2 + 1) * 64 + 32 + lane]);
                bMa[k] = mrow[r2];
                bMb[k] = mrow[r2 + 1];
            }

#pragma unroll
            for (int p = 0; p < NPAIR; p++) {
                // Issue pair p+2's loads FIRST (depth-2 cover).
                if (p + 2 < NPAIR) {
                    const int sl = (p + 2) % 3;
                    const int r2 = 2 * (p + 2);
                    bA0[sl] = __ldcs(&m4[(size_t)r2 * 64 + lane]);
                    bA1[sl] = __ldcs(&m4[(size_t)r2 * 64 + 32 + lane]);
                    bB0[sl] = __ldcs(&m4[(size_t)(r2 + 1) * 64 + lane]);
                    bB1[sl] = __ldcs(&m4[(size_t)(r2 + 1) * 64 + 32 + lane]);
                    bMa[sl] = mrow[r2];
                    bMb[sl] = mrow[r2 + 1];
                }
                const int sp = p % 3;
                const float4 Ca0 = bA0[sp], Ca1 = bA1[sp];
                const float4 Cb0 = bB0[sp], Cb1 = bB1[sp];

                float d1a = dot8(Ca0, w10, Ca1, w11);
                float d2a = dot8(Ca0, w20, Ca1, w21);
                float d1b = dot8(Cb0, w10, Cb1, w11);
                float d2b = dot8(Cb0, w20, Cb1, w21);
#pragma unroll
                for (int o = 16; o > 0; o >>= 1) {
                    d1a += __shfl_xor_sync(0xffffffffu, d1a, o);
                    d2a += __shfl_xor_sync(0xffffffffu, d2a, o);
                    d1b += __shfl_xor_sync(0xffffffffu, d1b, o);
                    d2b += __shfl_xor_sync(0xffffffffu, d2b, o);
                }
                const float pe1a = __expf(d1a) * bMa[sp];
                const float pe2a = __expf(d2a) * bMa[sp];
                const float pe1b = __expf(d1b) * bMb[sp];
                const float pe2b = __expf(d2b) * bMb[sp];
                l1 += pe1a + pe1b;
                l2 += pe2a + pe2b;
                FMA4(P0, pe1a, Ca0)  FMA4(P1, pe1a, Ca1)
                FMA4(Q0, pe2a, Ca0)  FMA4(Q1, pe2a, Ca1)
                FMA4(P0, pe1b, Cb0)  FMA4(P1, pe1b, Cb1)
                FMA4(Q0, pe2b, Cb0)  FMA4(Q1, pe2b, Cb1)
            }

            // ---- fused flush: both streams, one barrier pair ----
            *(float4*)&s_red[w * D_ + lane * 4]                 = P0;
            *(float4*)&s_red[w * D_ + 128 + lane * 4]           = P1;
            *(float4*)&s_red[NW * D_ + w * D_ + lane * 4]       = Q0;
            *(float4*)&s_red[NW * D_ + w * D_ + 128 + lane * 4] = Q1;
            if (lane == 0) { s_lred[w] = l1; s_lred[NW + w] = l2; }
            __syncthreads();
            {
                float v1a = 0.f, v1b = 0.f, v2a = 0.f, v2b = 0.f;
#pragma unroll
                for (int ww = 0; ww < NW; ww++) {
                    v1a += s_red[ww * D_ + tid];
                    v1b += s_red[ww * D_ + tid + 128];
                    v2a += s_red[NW * D_ + ww * D_ + tid];
                    v2b += s_red[NW * D_ + ww * D_ + tid + 128];
                }
                const float L1 = s_lred[0] + s_lred[1] + s_lred[2] + s_lred[3];
                const float L2 = s_lred[4] + s_lred[5] + s_lred[6] + s_lred[7];
                g_p1[e][tid] = v1a;  g_p1[e][tid + 128] = v1b;
                g_p2[e][tid] = v2a;  g_p2[e][tid + 128] = v2b;
                if (tid == 0) { g_p1[e][256] = L1; g_p2[e][256] = L2; }
            }
            __threadfence();   // release own partial STGs (every thread)
            __syncthreads();
            if (tid == 0) {
                const unsigned old = atomicAdd(&g_cnt_s[b], 1u);
                s_doc = ((old & 31u) == 31u);
            }
            __syncthreads();
            if (s_doc) {
                __threadfence();   // acquire (per thread)
                float V1a = 0.f, V1b = 0.f, V2a = 0.f, V2b = 0.f;
                float L1 = 0.f, L2 = 0.f;
#pragma unroll 8
                for (int s2 = 0; s2 < S_; s2++) {
                    const int i = b * S_ + s2;
                    V1a += __ldcg(&g_p1[i][tid]);
                    V1b += __ldcg(&g_p1[i][tid + 128]);
                    V2a += __ldcg(&g_p2[i][tid]);
                    V2b += __ldcg(&g_p2[i][tid + 128]);
                    L1  += __ldcg(&g_p1[i][256]);
                    L2  += __ldcg(&g_p2[i][256]);
                }
                out[b * D_ + tid]       = 0.5f * (V1a / L1) + 0.5f * (V2a / L2);
                out[b * D_ + tid + 128] = 0.5f * (V1b / L1) + 0.5f * (V2b / L2);
            }
            __syncthreads();
        }
    } else {
        // ------------- aspect: fast-tanh-score softmax -------------
        const float bm = b_mul[0];
        for (int j = 0; j < nit; j++) {
            const int e = tcta + CPT * j;
            const int b = e >> 5, s = e & 31;
            const float4* m4 = (const float4*)(aspect_memory
                             + ((size_t)b * T_ + (size_t)s * ROWS_ITEM
                                + w * ROWS_W) * D_);
            const float4 md0 = *(const float4*)(g_mids + b * D_ + lane * 4);
            const float4 md1 = *(const float4*)(g_mids + b * D_ + 128 + lane * 4);

            float l = 0.f;
            float4 A0 = {0,0,0,0}, A1 = {0,0,0,0};

            float4 bA0[3], bA1[3], bB0[3], bB1[3];
#pragma unroll
            for (int k = 0; k < 2; k++) {
                const int r2 = 2 * k;
                bA0[k] = __ldcs(&m4[(size_t)r2 * 64 + lane]);
                bA1[k] = __ldcs(&m4[(size_t)r2 * 64 + 32 + lane]);
                bB0[k] = __ldcs(&m4[(size_t)(r2 + 1) * 64 + lane]);
                bB1[k] = __ldcs(&m4[(size_t)(r2 + 1) * 64 + 32 + lane]);
            }

#pragma unroll
            for (int p = 0; p < NPAIR; p++) {
                if (p + 2 < NPAIR) {
                    const int sl = (p + 2) % 3;
                    const int r2 = 2 * (p + 2);
                    bA0[sl] = __ldcs(&m4[(size_t)r2 * 64 + lane]);
                    bA1[sl] = __ldcs(&m4[(size_t)r2 * 64 + 32 + lane]);
                    bB0[sl] = __ldcs(&m4[(size_t)(r2 + 1) * 64 + lane]);
                    bB1[sl] = __ldcs(&m4[(size_t)(r2 + 1) * 64 + 32 + lane]);
                }
                const int sp = p % 3;
                const float4 Ca0 = bA0[sp], Ca1 = bA1[sp];
                const float4 Cb0 = bB0[sp], Cb1 = bB1[sp];

                float pa = dot8(Ca0, md0, Ca1, md1);
                float pb = dot8(Cb0, md0, Cb1, md1);
#pragma unroll
                for (int o = 16; o > 0; o >>= 1) {
                    pa += __shfl_xor_sync(0xffffffffu, pa, o);
                    pb += __shfl_xor_sync(0xffffffffu, pb, o);
                }
                const float pea = __expf(fast_tanh(pa + bm));
                const float peb = __expf(fast_tanh(pb + bm));
                l += pea + peb;
                FMA4(A0, pea, Ca0)  FMA4(A1, pea, Ca1)
                FMA4(A0, peb, Cb0)  FMA4(A1, peb, Cb1)
            }

            // ---- flush (single stream) ----
            *(float4*)&s_red[w * D_ + lane * 4]       = A0;
            *(float4*)&s_red[w * D_ + 128 + lane * 4] = A1;
            if (lane == 0) s_lred[w] = l;
            __syncthreads();
            {
                float va = 0.f, vb = 0.f;
#pragma unroll
                for (int ww = 0; ww < NW; ww++) {
                    va += s_red[ww * D_ + tid];
                    vb += s_red[ww * D_ + tid + 128];
                }
                const float L = s_lred[0] + s_lred[1] + s_lred[2] + s_lred[3];
                g_pa[e][tid] = va;  g_pa[e][tid + 128] = vb;
                if (tid == 0) g_pa[e][256] = L;
            }
            __threadfence();   // release (every thread)
            __syncthreads();
            if (tid == 0) {
                const unsigned old = atomicAdd(&g_cnt_a[b], 1u);
                s_doc = ((old & 31u) == 31u);
            }
            __syncthreads();
            if (s_doc) {
                __threadfence();   // acquire (per thread)
                float Va = 0.f, Vb = 0.f, La = 0.f;
#pragma unroll 8
                for (int s2 = 0; s2 < S_; s2++) {
                    const int i = b * S_ + s2;
                    Va += __ldcg(&g_pa[i][tid]);
                    Vb += __ldcg(&g_pa[i][tid + 128]);
                    La += __ldcg(&g_pa[i][256]);
                }
                out[B_ * D_ + b * D_ + tid] = aspect[b * D_ + tid] + Va / La;
                out[B_ * D_ + b * D_ + tid + 128] =
                    aspect[b * D_ + tid + 128] + Vb / La;
            }
            __syncthreads();
        }
    }
}

// ---------------------------------------------------------------------------
// kernel_launch. Inputs (metadata order):
//  0 sentiment  1 aspect  2 sentiment_memory  3 aspect_memory  4 mask
//  5 W_mul  6 b_mul  7 w_ss  8 b_ss  9 w_sa  10 b_sa
// Query-side additive terms (w[D:], biases) cancel in the softmax -> unused.
// Output: sentiment_out [0, B*D), aspect_out [B*D, 2*B*D).
// ---------------------------------------------------------------------------
extern "C" void kernel_launch(void* const* d_in, const int* in_sizes, int n_in,
                              void* d_out, int out_size)
{
    const float* aspect           = (const float*)d_in[1];
    const float* sentiment_memory = (const float*)d_in[2];
    const float* aspect_memory    = (const float*)d_in[3];
    const float* mask             = (const float*)d_in[4];
    const float* W_mul            = (const float*)d_in[5];
    const float* b_mul            = (const float*)d_in[6];
    const float* w_ss             = (const float*)d_in[7];
    const float* w_sa             = (const float*)d_in[9];
    float* out = (float*)d_out;

    k_main<<<GRID_MAIN, NTHREADS>>>(
        aspect, sentiment_memory, aspect_memory, mask, W_mul, b_mul,
        w_ss, w_sa, out);
}